// round 1
// baseline (speedup 1.0000x reference)
#include <cuda_runtime.h>

#define NN 100000
#define NE 1600000
#define NG 64

// ---------------- scratch (static device globals; no allocation) ----------------
__device__ __align__(256) float g_xA[(size_t)NN * 128];
__device__ __align__(256) float g_xB[(size_t)NN * 128];
__device__ __align__(256) float g_xp[(size_t)NN * 128];
__device__ __align__(256) float g_msg[(size_t)NN * 128];
__device__ int g_deg[NN];
__device__ int g_cursor[NN];
__device__ int g_rowptr[NN + 1];
__device__ int g_adj[NE];
__device__ unsigned g_gmax[NG * 64];
__device__ float g_gsum[NG * 64];
__device__ int g_gcnt[NG];

// order-preserving float<->uint encoding for atomicMax on floats
__device__ __forceinline__ unsigned fenc(float f) {
    unsigned u = __float_as_uint(f);
    return (u & 0x80000000u) ? ~u : (u | 0x80000000u);
}
__device__ __forceinline__ float fdec(unsigned e) {
    return __uint_as_float((e & 0x80000000u) ? (e ^ 0x80000000u) : ~e);
}

// ---------------- init ----------------
__global__ void init_kernel() {
    int j = blockIdx.x * blockDim.x + threadIdx.x;
    if (j < NN) { g_deg[j] = 0; g_cursor[j] = 0; }
    if (j < NG * 64) { g_gmax[j] = 0x007FFFFFu; /* fenc(-inf) */ g_gsum[j] = 0.f; }
    if (j < NG) g_gcnt[j] = 0;
}

// ---------------- CSR build ----------------
__global__ void hist_kernel(const int* __restrict__ dst) {
    int e = blockIdx.x * blockDim.x + threadIdx.x;
    if (e < NE) atomicAdd(&g_deg[dst[e]], 1);
}

__global__ void scan_kernel() {
    __shared__ int sh[1024];
    __shared__ int carry;
    int tid = threadIdx.x;
    if (tid == 0) carry = 0;
    __syncthreads();
    for (int base = 0; base < NN; base += 1024) {
        int i = base + tid;
        int v = (i < NN) ? g_deg[i] : 0;
        sh[tid] = v;
        __syncthreads();
        for (int off = 1; off < 1024; off <<= 1) {
            int t = (tid >= off) ? sh[tid - off] : 0;
            __syncthreads();
            sh[tid] += t;
            __syncthreads();
        }
        int inc = sh[tid];
        int tot = sh[1023];
        int c = carry;
        if (i < NN) g_rowptr[i] = c + inc - v;  // exclusive
        __syncthreads();
        if (tid == 0) carry = c + tot;
        __syncthreads();
    }
    if (tid == 0) g_rowptr[NN] = carry;
}

__global__ void fill_adj_kernel(const int* __restrict__ src, const int* __restrict__ dst) {
    int e = blockIdx.x * blockDim.x + threadIdx.x;
    if (e < NE) {
        int d = dst[e];
        int p = atomicAdd(&g_cursor[d], 1);
        g_adj[g_rowptr[d] + p] = src[e];
    }
}

// ---------------- fused input-concat + lin GEMM (K=190 virtual, BN=128, relu) ----------------
__global__ void __launch_bounds__(256)
lin_kernel(const float* __restrict__ nf, const float* __restrict__ cf,
           const int* __restrict__ opc, const float* __restrict__ emb,
           const float* __restrict__ W, const float* __restrict__ bias,
           float* __restrict__ C) {
    constexpr int BM = 64, BN = 128, BK = 32, TM = 8, TN = 4, KP = 192;
    __shared__ float As[BK][BM + 1];
    __shared__ float Ws[BK][BN];
    const int tid = threadIdx.x;
    const int tx = tid & 31, ty = tid >> 5;
    const int rowBase = blockIdx.x * BM;
    const int arow = tid >> 2;
    const int acol = (tid & 3) * 8;
    const int grow = rowBase + arow;
    const bool rowOK = grow < NN;
    const int myop = rowOK ? opc[grow] : 0;

    float acc[TM][TN];
#pragma unroll
    for (int i = 0; i < TM; i++)
#pragma unroll
        for (int j = 0; j < TN; j++) acc[i][j] = 0.f;

#pragma unroll 1
    for (int k0 = 0; k0 < KP; k0 += BK) {
        __syncthreads();
#pragma unroll
        for (int s = 0; s < 8; s++) {
            int k = k0 + acol + s;
            float v = 0.f;
            if (rowOK) {
                if (k < 140)      v = nf[grow * 140 + k];
                else if (k < 172) v = emb[myop * 32 + (k - 140)];
                else if (k < 190) v = cf[grow * 18 + (k - 172)];
            }
            As[acol + s][arow] = v;
        }
#pragma unroll
        for (int v4 = 0; v4 < 4; v4++) {
            int fid = tid + v4 * 256;
            int kk = fid >> 5;          // /(BN/4)=32
            int c4 = fid & 31;
            float4 w = make_float4(0, 0, 0, 0);
            if (k0 + kk < 190)
                w = *reinterpret_cast<const float4*>(W + (size_t)(k0 + kk) * BN + c4 * 4);
            *reinterpret_cast<float4*>(&Ws[kk][c4 * 4]) = w;
        }
        __syncthreads();
#pragma unroll
        for (int kk = 0; kk < BK; kk++) {
            float a[TM], w[TN];
#pragma unroll
            for (int i = 0; i < TM; i++) a[i] = As[kk][ty * TM + i];
#pragma unroll
            for (int j = 0; j < TN; j++) w[j] = Ws[kk][tx * TN + j];
#pragma unroll
            for (int i = 0; i < TM; i++)
#pragma unroll
                for (int j = 0; j < TN; j++) acc[i][j] = fmaf(a[i], w[j], acc[i][j]);
        }
    }
#pragma unroll
    for (int i = 0; i < TM; i++) {
        int r = rowBase + ty * TM + i;
        if (r < NN) {
            float v0 = fmaxf(acc[i][0] + bias[tx * 4 + 0], 0.f);
            float v1 = fmaxf(acc[i][1] + bias[tx * 4 + 1], 0.f);
            float v2 = fmaxf(acc[i][2] + bias[tx * 4 + 2], 0.f);
            float v3 = fmaxf(acc[i][3] + bias[tx * 4 + 3], 0.f);
            *reinterpret_cast<float4*>(C + (size_t)r * BN + tx * 4) = make_float4(v0, v1, v2, v3);
        }
    }
}

// ---------------- generic GEMM + bias + relu (C[NN,BN] = relu(A[NN,K] @ W[K,BN] + b)) ----------------
template <int K, int BN>
__global__ void __launch_bounds__(256)
gemm_relu_kernel(const float* __restrict__ A, const float* __restrict__ W,
                 const float* __restrict__ bias, float* __restrict__ C) {
    constexpr int BM = 64, BK = 32;
    constexpr int TM = 8, TN = BN / 32;
    constexpr int WV = (BK * BN) / 1024;  // float4 loads per thread for W
    __shared__ float As[BK][BM + 1];
    __shared__ float Ws[BK][BN];
    const int tid = threadIdx.x;
    const int tx = tid & 31, ty = tid >> 5;
    const int rowBase = blockIdx.x * BM;
    const int arow = tid >> 2;
    const int acol = (tid & 3) * 8;
    const int grow = rowBase + arow;
    const bool rowOK = grow < NN;

    float acc[TM][TN];
#pragma unroll
    for (int i = 0; i < TM; i++)
#pragma unroll
        for (int j = 0; j < TN; j++) acc[i][j] = 0.f;

#pragma unroll 1
    for (int k0 = 0; k0 < K; k0 += BK) {
        __syncthreads();
        float4 a0 = make_float4(0, 0, 0, 0), a1 = make_float4(0, 0, 0, 0);
        if (rowOK) {
            const float* ap = A + (size_t)grow * K + k0 + acol;
            a0 = *reinterpret_cast<const float4*>(ap);
            a1 = *reinterpret_cast<const float4*>(ap + 4);
        }
        As[acol + 0][arow] = a0.x; As[acol + 1][arow] = a0.y;
        As[acol + 2][arow] = a0.z; As[acol + 3][arow] = a0.w;
        As[acol + 4][arow] = a1.x; As[acol + 5][arow] = a1.y;
        As[acol + 6][arow] = a1.z; As[acol + 7][arow] = a1.w;
#pragma unroll
        for (int v4 = 0; v4 < WV; v4++) {
            int fid = tid + v4 * 256;
            int kk = fid / (BN / 4);
            int c4 = fid % (BN / 4);
            *reinterpret_cast<float4*>(&Ws[kk][c4 * 4]) =
                *reinterpret_cast<const float4*>(W + (size_t)(k0 + kk) * BN + c4 * 4);
        }
        __syncthreads();
#pragma unroll
        for (int kk = 0; kk < BK; kk++) {
            float a[TM], w[TN];
#pragma unroll
            for (int i = 0; i < TM; i++) a[i] = As[kk][ty * TM + i];
#pragma unroll
            for (int j = 0; j < TN; j++) w[j] = Ws[kk][tx * TN + j];
#pragma unroll
            for (int i = 0; i < TM; i++)
#pragma unroll
                for (int j = 0; j < TN; j++) acc[i][j] = fmaf(a[i], w[j], acc[i][j]);
        }
    }
#pragma unroll
    for (int i = 0; i < TM; i++) {
        int r = rowBase + ty * TM + i;
        if (r < NN) {
#pragma unroll
            for (int j = 0; j < TN; j++)
                acc[i][j] = fmaxf(acc[i][j] + bias[tx * TN + j], 0.f);
            if constexpr (TN == 4)
                *reinterpret_cast<float4*>(C + (size_t)r * BN + tx * 4) =
                    make_float4(acc[i][0], acc[i][1], acc[i][2], acc[i][3]);
            else
                *reinterpret_cast<float2*>(C + (size_t)r * BN + tx * 2) =
                    make_float2(acc[i][0], acc[i][1]);
        }
    }
}

// ---------------- mean aggregation over CSR (gather only, no atomics) ----------------
__global__ void agg_kernel128(const float* __restrict__ xp, float* __restrict__ msg) {
    int w = (blockIdx.x * blockDim.x + threadIdx.x) >> 5;
    int lane = threadIdx.x & 31;
    if (w >= NN) return;
    int beg = g_rowptr[w], end = g_rowptr[w + 1];
    float4 acc = make_float4(0, 0, 0, 0);
    for (int e = beg; e < end; e++) {
        int s = __ldg(&g_adj[e]);
        float4 v = *reinterpret_cast<const float4*>(xp + (size_t)s * 128 + lane * 4);
        acc.x += v.x; acc.y += v.y; acc.z += v.z; acc.w += v.w;
    }
    float inv = 1.0f / fmaxf((float)(end - beg), 1.0f);
    *reinterpret_cast<float4*>(msg + (size_t)w * 128 + lane * 4) =
        make_float4(acc.x * inv, acc.y * inv, acc.z * inv, acc.w * inv);
}

__global__ void agg_kernel64(const float* __restrict__ xp, float* __restrict__ msg) {
    int w = (blockIdx.x * blockDim.x + threadIdx.x) >> 5;
    int lane = threadIdx.x & 31;
    if (w >= NN) return;
    int beg = g_rowptr[w], end = g_rowptr[w + 1];
    float2 acc = make_float2(0, 0);
    for (int e = beg; e < end; e++) {
        int s = __ldg(&g_adj[e]);
        float2 v = *reinterpret_cast<const float2*>(xp + (size_t)s * 64 + lane * 2);
        acc.x += v.x; acc.y += v.y;
    }
    float inv = 1.0f / fmaxf((float)(end - beg), 1.0f);
    *reinterpret_cast<float2*>(msg + (size_t)w * 64 + lane * 2) =
        make_float2(acc.x * inv, acc.y * inv);
}

// ---------------- combine: out = normalize(mean@Wl + bl + x@Wr) ----------------
template <int K>
__global__ void __launch_bounds__(256)
combine_norm_kernel(const float* __restrict__ M, const float* __restrict__ X,
                    const float* __restrict__ Wl, const float* __restrict__ Wr,
                    const float* __restrict__ bl, float* __restrict__ C) {
    constexpr int BM = 64, BN = 64, BK = 32, TM = 8, TN = 2;
    __shared__ float Ms[BK][BM + 1];
    __shared__ float Xs[BK][BM + 1];
    __shared__ float Wls[BK][BN];
    __shared__ float Wrs[BK][BN];
    const int tid = threadIdx.x;
    const int tx = tid & 31, ty = tid >> 5;
    const int rowBase = blockIdx.x * BM;
    const int arow = tid >> 2;
    const int acol = (tid & 3) * 8;
    const int grow = rowBase + arow;
    const bool rowOK = grow < NN;

    float acc[TM][TN];
#pragma unroll
    for (int i = 0; i < TM; i++)
#pragma unroll
        for (int j = 0; j < TN; j++) acc[i][j] = 0.f;

#pragma unroll 1
    for (int k0 = 0; k0 < K; k0 += BK) {
        __syncthreads();
        float4 m0 = make_float4(0, 0, 0, 0), m1 = make_float4(0, 0, 0, 0);
        float4 x0 = make_float4(0, 0, 0, 0), x1 = make_float4(0, 0, 0, 0);
        if (rowOK) {
            const float* mp = M + (size_t)grow * K + k0 + acol;
            const float* xpp = X + (size_t)grow * K + k0 + acol;
            m0 = *reinterpret_cast<const float4*>(mp);
            m1 = *reinterpret_cast<const float4*>(mp + 4);
            x0 = *reinterpret_cast<const float4*>(xpp);
            x1 = *reinterpret_cast<const float4*>(xpp + 4);
        }
        Ms[acol + 0][arow] = m0.x; Ms[acol + 1][arow] = m0.y;
        Ms[acol + 2][arow] = m0.z; Ms[acol + 3][arow] = m0.w;
        Ms[acol + 4][arow] = m1.x; Ms[acol + 5][arow] = m1.y;
        Ms[acol + 6][arow] = m1.z; Ms[acol + 7][arow] = m1.w;
        Xs[acol + 0][arow] = x0.x; Xs[acol + 1][arow] = x0.y;
        Xs[acol + 2][arow] = x0.z; Xs[acol + 3][arow] = x0.w;
        Xs[acol + 4][arow] = x1.x; Xs[acol + 5][arow] = x1.y;
        Xs[acol + 6][arow] = x1.z; Xs[acol + 7][arow] = x1.w;
#pragma unroll
        for (int v4 = 0; v4 < 2; v4++) {
            int fid = tid + v4 * 256;
            int kk = fid >> 4;  // /(BN/4)=16
            int c4 = fid & 15;
            *reinterpret_cast<float4*>(&Wls[kk][c4 * 4]) =
                *reinterpret_cast<const float4*>(Wl + (size_t)(k0 + kk) * BN + c4 * 4);
            *reinterpret_cast<float4*>(&Wrs[kk][c4 * 4]) =
                *reinterpret_cast<const float4*>(Wr + (size_t)(k0 + kk) * BN + c4 * 4);
        }
        __syncthreads();
#pragma unroll
        for (int kk = 0; kk < BK; kk++) {
            float am[TM], ax[TM], wl[TN], wr[TN];
#pragma unroll
            for (int i = 0; i < TM; i++) { am[i] = Ms[kk][ty * TM + i]; ax[i] = Xs[kk][ty * TM + i]; }
#pragma unroll
            for (int j = 0; j < TN; j++) { wl[j] = Wls[kk][tx * TN + j]; wr[j] = Wrs[kk][tx * TN + j]; }
#pragma unroll
            for (int i = 0; i < TM; i++)
#pragma unroll
                for (int j = 0; j < TN; j++)
                    acc[i][j] = fmaf(ax[i], wr[j], fmaf(am[i], wl[j], acc[i][j]));
        }
    }
    // epilogue: +bias, row L2 normalize (each row fully owned by one warp: 32 lanes x 2 cols)
#pragma unroll
    for (int i = 0; i < TM; i++) {
        float v0 = acc[i][0] + bl[tx * 2 + 0];
        float v1 = acc[i][1] + bl[tx * 2 + 1];
        float ss = v0 * v0 + v1 * v1;
#pragma unroll
        for (int o = 16; o > 0; o >>= 1) ss += __shfl_xor_sync(0xffffffffu, ss, o);
        float sc = 1.0f / fmaxf(sqrtf(ss), 1e-12f);
        int r = rowBase + ty * TM + i;
        if (r < NN)
            *reinterpret_cast<float2*>(C + (size_t)r * 64 + tx * 2) =
                make_float2(v0 * sc, v1 * sc);
    }
}

// ---------------- pooling: per-graph max + sum + count ----------------
__global__ void pool_kernel(const float* __restrict__ x, const int* __restrict__ batch) {
    int nwarps = (gridDim.x * blockDim.x) >> 5;
    int w = (blockIdx.x * blockDim.x + threadIdx.x) >> 5;
    int lane = threadIdx.x & 31;
    int per = (NN + nwarps - 1) / nwarps;
    int s = w * per;
    int e = min(NN, s + per);
    if (s >= e) return;
    float m0 = -__int_as_float(0x7f800000), m1 = m0;  // -inf
    float s0 = 0.f, s1 = 0.f;
    int cnt = 0;
    int curg = __ldg(&batch[s]);
    for (int i = s; i < e; i++) {
        int g = __ldg(&batch[i]);
        if (g != curg) {
            atomicMax(&g_gmax[curg * 64 + lane], fenc(m0));
            atomicMax(&g_gmax[curg * 64 + lane + 32], fenc(m1));
            atomicAdd(&g_gsum[curg * 64 + lane], s0);
            atomicAdd(&g_gsum[curg * 64 + lane + 32], s1);
            if (lane == 0) atomicAdd(&g_gcnt[curg], cnt);
            m0 = m1 = -__int_as_float(0x7f800000);
            s0 = s1 = 0.f; cnt = 0; curg = g;
        }
        float v0 = x[(size_t)i * 64 + lane];
        float v1 = x[(size_t)i * 64 + lane + 32];
        m0 = fmaxf(m0, v0); m1 = fmaxf(m1, v1);
        s0 += v0; s1 += v1; cnt++;
    }
    atomicMax(&g_gmax[curg * 64 + lane], fenc(m0));
    atomicMax(&g_gmax[curg * 64 + lane + 32], fenc(m1));
    atomicAdd(&g_gsum[curg * 64 + lane], s0);
    atomicAdd(&g_gsum[curg * 64 + lane + 32], s1);
    if (lane == 0) atomicAdd(&g_gcnt[curg], cnt);
}

// ---------------- final: xg = max+mean; normalize; @post_w + post_b ----------------
__global__ void final_kernel(const float* __restrict__ post_w, const float* __restrict__ post_b,
                             float* __restrict__ out) {
    int g = threadIdx.x;
    if (g >= NG) return;
    float inv = 1.0f / (float)g_gcnt[g];
    float v[64];
    float ss = 0.f;
#pragma unroll
    for (int c = 0; c < 64; c++) {
        float t = fdec(g_gmax[g * 64 + c]) + g_gsum[g * 64 + c] * inv;
        v[c] = t;
        ss += t * t;
    }
    float norm = sqrtf(ss);
    float dot = 0.f;
#pragma unroll
    for (int c = 0; c < 64; c++) dot += v[c] * post_w[c];
    out[g] = dot / norm + post_b[0];
}

// ---------------- launch ----------------
extern "C" void kernel_launch(void* const* d_in, const int* in_sizes, int n_in,
                              void* d_out, int out_size) {
    const float* node_feat = (const float*)d_in[0];
    const float* cfg_feat  = (const float*)d_in[1];
    const int*   opcode    = (const int*)d_in[2];
    const int*   edge      = (const int*)d_in[3];  // [0..E)=src, [E..2E)=dst
    const int*   batch     = (const int*)d_in[4];
    const float* op_emb    = (const float*)d_in[5];
    const float* lin_w     = (const float*)d_in[6];
    const float* lin_b     = (const float*)d_in[7];
    const float* post_w    = (const float*)d_in[8];
    const float* post_b    = (const float*)d_in[9];
    const float* pw0 = (const float*)d_in[10];
    const float* pb0 = (const float*)d_in[11];
    const float* wl0 = (const float*)d_in[12];
    const float* bl0 = (const float*)d_in[13];
    const float* wr0 = (const float*)d_in[14];
    const float* pw1 = (const float*)d_in[15];
    const float* pb1 = (const float*)d_in[16];
    const float* wl1 = (const float*)d_in[17];
    const float* bl1 = (const float*)d_in[18];
    const float* wr1 = (const float*)d_in[19];
    const float* pw2 = (const float*)d_in[20];
    const float* pb2 = (const float*)d_in[21];
    const float* wl2 = (const float*)d_in[22];
    const float* bl2 = (const float*)d_in[23];
    const float* wr2 = (const float*)d_in[24];
    float* out = (float*)d_out;

    const int* src = edge;
    const int* dst = edge + NE;

    const int GB = (NN + 63) / 64;                    // 1563 GEMM blocks
    const int EB = (NE + 255) / 256;                  // edge blocks
    const int AGGB = (NN * 32 + 255) / 256;           // warp-per-node blocks

    // CSR build
    init_kernel<<<(NN + 255) / 256, 256>>>();
    hist_kernel<<<EB, 256>>>(dst);
    scan_kernel<<<1, 1024>>>();
    fill_adj_kernel<<<EB, 256>>>(src, dst);

    // input encoder
    float* dA; cudaGetSymbolAddress((void**)&dA, g_xA);
    float* dB; cudaGetSymbolAddress((void**)&dB, g_xB);
    float* dP; cudaGetSymbolAddress((void**)&dP, g_xp);
    float* dM; cudaGetSymbolAddress((void**)&dM, g_msg);

    lin_kernel<<<GB, 256>>>(node_feat, cfg_feat, opcode, op_emb, lin_w, lin_b, dA);

    // layer 0 (d=128 -> 64)
    gemm_relu_kernel<128, 128><<<GB, 256>>>(dA, pw0, pb0, dP);
    agg_kernel128<<<AGGB, 256>>>(dP, dM);
    combine_norm_kernel<128><<<GB, 256>>>(dM, dA, wl0, wr0, bl0, dB);

    // layer 1 (d=64 -> 64)
    gemm_relu_kernel<64, 64><<<GB, 256>>>(dB, pw1, pb1, dP);
    agg_kernel64<<<AGGB, 256>>>(dP, dM);
    combine_norm_kernel<64><<<GB, 256>>>(dM, dB, wl1, wr1, bl1, dA);

    // layer 2 (d=64 -> 64)
    gemm_relu_kernel<64, 64><<<GB, 256>>>(dA, pw2, pb2, dP);
    agg_kernel64<<<AGGB, 256>>>(dP, dM);
    combine_norm_kernel<64><<<GB, 256>>>(dM, dA, wl2, wr2, bl2, dB);

    // readout
    pool_kernel<<<128, 256>>>(dB, batch);
    final_kernel<<<1, 64>>>(post_w, post_b, out);
}